// round 6
// baseline (speedup 1.0000x reference)
#include <cuda_runtime.h>

#define NCLS  16
#define MTOT  (8*512*512)          // 2097152 pixels
#define CHST  (512*512)            // channel stride
#define NPAIR (MTOT/2)
#define N4    (MTOT/4)
#define NBLK  296                  // 2 blocks/SM on 148 SMs -> all co-resident
#define NTHR  256
#define TOTTHR (NBLK*NTHR)

#define LOG2E 1.4426950408889634f
#define LN2   0.6931471805599453f
#define LOG2_EPS (-6.643856189774724f)   // log2(0.01)

__device__ int           g_part[NBLK][NCLS];
__device__ float         g_pnll[NBLK];
__device__ volatile int  g_sync;           // starts 0 (module init); reset each run
__device__ int           g_done;

__device__ __forceinline__ float ex2(float x){ float r; asm("ex2.approx.f32 %0,%1;":"=f"(r):"f"(x)); return r; }
__device__ __forceinline__ float lg2(float x){ float r; asm("lg2.approx.f32 %0,%1;":"=f"(r):"f"(x)); return r; }

// per-pixel seesaw NLL in base-2 log domain; y[c] = logit[c]*LOG2E
__device__ __forceinline__ float pix_nll(const float* y, int lab, const float* slog2) {
    float yl = y[0];
#pragma unroll
    for (int c = 1; c < NCLS; c++) if (lab == c) yl = y[c];

    float mx = y[0];
#pragma unroll
    for (int c = 1; c < NCLS; c++) mx = fmaxf(mx, y[c]);
    float s = 0.0f;
#pragma unroll
    for (int c = 0; c < NCLS; c++) s += ex2(y[c] - mx);
    float lse1 = mx + lg2(s);                       // base-2 logsumexp

    float slc = fmaxf(yl - lse1, LOG2_EPS);         // log2(clip(self_score, EPS))
    float off = lse1 + slc;
    float lcL = slog2[lab];

    float a[NCLS];
    float mx2 = -1e30f;
#pragma unroll
    for (int c = 0; c < NCLS; c++) {
        // log2(mitigation) + log2(compensation); both 0 at c==lab
        float w = 0.8f * fminf(0.0f, slog2[c] - lcL)
                + 2.0f * fmaxf(0.0f, y[c] - off);
        float t = y[c] + w;
        a[c] = t;
        mx2 = fmaxf(mx2, t);
    }
    float s2 = 0.0f;
#pragma unroll
    for (int c = 0; c < NCLS; c++) s2 += ex2(a[c] - mx2);
    return mx2 + lg2(s2) - yl;                      // nll in base-2 units
}

__global__ void __launch_bounds__(NTHR, 2)
k_fused(const float* __restrict__ score,
        const int*   __restrict__ labels,
        const float* __restrict__ cum_samples,
        float*       __restrict__ out) {
    __shared__ int   sh_part[NCLS];
    __shared__ int   sh_hist[NCLS];
    __shared__ float slog2[NCLS];
    __shared__ float swarp[NTHR/32];
    __shared__ int   sh_last;

    const int tid  = threadIdx.x;
    const int bid  = blockIdx.x;
    const int lane = tid & 31;
    const int gid  = bid * NTHR + tid;

    // ---------------- phase 1: histogram (ballot counting, uniform trip count)
    if (tid < NCLS) sh_part[tid] = 0;
    __syncthreads();
    {
        unsigned cnt = 0;
        const int4* lab4 = (const int4*)labels;
        const int niter = (N4 + TOTTHR - 1) / TOTTHR;   // uniform -> ballots converged
#pragma unroll 1
        for (int it = 0; it < niter; it++) {
            int i = gid + it * TOTTHR;
            int4 L = (i < N4) ? __ldg(lab4 + i) : make_int4(-1,-1,-1,-1);
#pragma unroll
            for (int q = 0; q < 4; q++) {
                int lv = (q==0)?L.x:(q==1)?L.y:(q==2)?L.z:L.w;
#pragma unroll
                for (int c = 0; c < NCLS; c++) {
                    unsigned b = __ballot_sync(0xffffffffu, lv == c);
                    if (lane == c) cnt += __popc(b);
                }
            }
        }
        if (lane < NCLS) atomicAdd(&sh_part[lane], (int)cnt);
    }
    __syncthreads();
    if (tid < NCLS) g_part[bid][tid] = sh_part[tid];

    // ---------------- grid barrier
    if (tid == 0) {
        __threadfence();
        atomicAdd((int*)&g_sync, 1);
        while (g_sync < NBLK) __nanosleep(64);
        __threadfence();
    }
    __syncthreads();

    // ---------------- rebuild full histogram + log2(cum) in every block
    if (tid < NCLS) sh_hist[tid] = 0;
    __syncthreads();
    {
        int c = tid & 15, ch = tid >> 4;
        int cc = 0;
        for (int b = ch; b < NBLK; b += 16) cc += g_part[b][c];
        atomicAdd(&sh_hist[c], cc);
    }
    __syncthreads();
    if (tid < NCLS)
        slog2[tid] = lg2(fmaxf(cum_samples[tid] + (float)sh_hist[tid], 1.0f));
    __syncthreads();

    // ---------------- phase 2: main per-pixel loop, float2 (2 pixels/thread)
    float acc = 0.0f;
#pragma unroll 1
    for (int p = gid; p < NPAIR; p += TOTTHR) {
        int2 L = __ldg((const int2*)labels + p);
        if ((L.x | L.y) == 0) continue;            // both ignored

        int m = p << 1;
        const float* bp = score + (m >> 18) * (NCLS * CHST) + (m & (CHST - 1));
        float yx[NCLS], yy[NCLS];
#pragma unroll
        for (int c = 0; c < NCLS; c++) {
            float2 t = __ldg((const float2*)(bp + c * CHST));
            yx[c] = t.x * LOG2E;
            yy[c] = t.y * LOG2E;
        }
        if (L.x) acc += pix_nll(yx, L.x, slog2);
        if (L.y) acc += pix_nll(yy, L.y, slog2);
    }

    // ---------------- block reduction
#pragma unroll
    for (int o = 16; o > 0; o >>= 1) acc += __shfl_xor_sync(0xffffffffu, acc, o);
    int warp = tid >> 5;
    if (lane == 0) swarp[warp] = acc;
    __syncthreads();
    if (warp == 0) {
        float v = (lane < NTHR/32) ? swarp[lane] : 0.0f;
#pragma unroll
        for (int o = 4; o > 0; o >>= 1) v += __shfl_xor_sync(0xffffffffu, v, o);
        if (lane == 0) {
            g_pnll[bid] = v;
            __threadfence();
            int old = atomicAdd(&g_done, 1);
            sh_last = (old == NBLK - 1);
        }
    }
    __syncthreads();

    // ---------------- last block finalizes (deterministic index order)
    if (sh_last) {
        float v = 0.0f;
        for (int b = tid; b < NBLK; b += NTHR) v += g_pnll[b];
#pragma unroll
        for (int o = 16; o > 0; o >>= 1) v += __shfl_xor_sync(0xffffffffu, v, o);
        if (lane == 0) swarp[warp] = v;
        __syncthreads();
        if (warp == 0) {
            float t = (lane < NTHR/32) ? swarp[lane] : 0.0f;
#pragma unroll
            for (int o = 4; o > 0; o >>= 1) t += __shfl_xor_sync(0xffffffffu, t, o);
            if (lane == 0) {
                out[0] = LN2 * t / (float)(MTOT - sh_hist[0]);
                g_sync = 0;            // reset for next graph replay
                g_done = 0;
            }
        }
    }
}

extern "C" void kernel_launch(void* const* d_in, const int* in_sizes, int n_in,
                              void* d_out, int out_size) {
    const float* cls  = nullptr;
    const int*   lab  = nullptr;
    const float* cums = nullptr;
    for (int i = 0; i < n_in; i++) {
        if (in_sizes[i] == MTOT * NCLS)  cls  = (const float*)d_in[i];
        else if (in_sizes[i] == MTOT)    lab  = (const int*)d_in[i];
        else if (in_sizes[i] == NCLS)    cums = (const float*)d_in[i];
    }
    if (!cls)  cls  = (const float*)d_in[0];
    if (!lab)  lab  = (const int*)d_in[1];
    if (!cums) cums = (const float*)d_in[2];

    k_fused<<<NBLK, NTHR>>>(cls, lab, cums, (float*)d_out);
    (void)out_size; (void)n_in;
}

// round 10
// speedup vs baseline: 1.1641x; 1.1641x over previous
#include <cuda_runtime.h>

#define NCLS  16
#define MTOT  (8*512*512)          // 2097152 pixels
#define CHST  (512*512)            // channel stride
#define N4    (MTOT/4)

#define HBLK  512
#define HTHR  256

#define MBLK  2048
#define MTHR  256

#define LOG2E 1.4426950408889634f
#define LN2   0.6931471805599453f
#define LOG2_EPS (-6.643856189774724f)   // log2(0.01)

__device__ int   g_hist[NCLS];           // zero at module load; self-reset per run
__device__ float g_pnll[MBLK];
__device__ int   g_done;                 // zero at module load; self-reset per run

__device__ __forceinline__ float ex2(float x){ float r; asm("ex2.approx.f32 %0,%1;":"=f"(r):"f"(x)); return r; }
__device__ __forceinline__ float lg2(float x){ float r; asm("lg2.approx.f32 %0,%1;":"=f"(r):"f"(x)); return r; }

// ---------------- kernel 1: label histogram (ballot counting) ----------------
// grid*block divides N4 exactly -> uniform trip count -> converged ballots.
__global__ void __launch_bounds__(HTHR) k_hist(const int* __restrict__ labels) {
    __shared__ int sh[NCLS];
    int t = threadIdx.x;
    if (t < NCLS) sh[t] = 0;
    __syncthreads();

    int lane = t & 31;
    unsigned cnt = 0;
    const int4* lab4 = (const int4*)labels;
    int idx    = blockIdx.x * HTHR + t;
    const int stride = HBLK * HTHR;                 // N4 % stride == 0
#pragma unroll 1
    for (int i = idx; i < N4; i += stride) {
        int4 L = __ldg(lab4 + i);
#pragma unroll
        for (int q = 0; q < 4; q++) {
            int lv = (q==0)?L.x:(q==1)?L.y:(q==2)?L.z:L.w;
#pragma unroll
            for (int c = 0; c < NCLS; c++) {
                unsigned b = __ballot_sync(0xffffffffu, lv == c);
                if (lane == c) cnt += __popc(b);
            }
        }
    }
    if (lane < NCLS) atomicAdd(&sh[lane], (int)cnt);
    __syncthreads();
    if (t < NCLS) atomicAdd(&g_hist[t], sh[t]);
}

// ---------------- kernel 2: main loop + finalize + state reset ----------------
__global__ void __launch_bounds__(MTHR) k_main(const float* __restrict__ score,
                                               const int*   __restrict__ labels,
                                               const float* __restrict__ cum_samples,
                                               float*       __restrict__ out) {
    __shared__ float slog2[NCLS];
    __shared__ float mit[NCLS][NCLS + 1];   // [c][lab], pad -> conflict-free LDS
    __shared__ float swarp[MTHR/32];
    __shared__ int   sh_last;

    const int tid  = threadIdx.x;
    const int bid  = blockIdx.x;
    const int lane = tid & 31;
    const int warp = tid >> 5;

    if (tid < NCLS)
        slog2[tid] = lg2(fmaxf(cum_samples[tid] + (float)g_hist[tid], 1.0f));
    if (tid == 0) sh_last = 0;
    __syncthreads();
    {   // 256 threads -> one mit entry each
        int c = tid >> 4, lab = tid & 15;
        mit[c][lab] = 0.8f * fminf(0.0f, slog2[c] - slog2[lab]);
    }
    __syncthreads();

    float acc = 0.0f;
#pragma unroll 1
    for (int m = bid * MTHR + tid; m < MTOT; m += MBLK * MTHR) {
        int lab = __ldg(labels + m);
        if (lab == 0) continue;                     // ignore_index

        const float* bp = score + (m >> 18) * (NCLS * CHST) + (m & (CHST - 1));
        float y[NCLS];
#pragma unroll
        for (int c = 0; c < NCLS; c++) y[c] = __ldg(bp + c * CHST) * LOG2E;

        float yl = y[0], mx = y[0];
#pragma unroll
        for (int c = 1; c < NCLS; c++) {
            if (lab == c) yl = y[c];
            mx = fmaxf(mx, y[c]);
        }
        float s = 0.0f;
#pragma unroll
        for (int c = 0; c < NCLS; c++) s += ex2(y[c] - mx);
        float lse1 = mx + lg2(s);

        // off = lse1 + max(yl - lse1, log2 EPS) = max(yl, lse1 + LOG2_EPS)
        float off = fmaxf(yl, lse1 + LOG2_EPS);

        float mx2 = -1e30f;
#pragma unroll
        for (int c = 0; c < NCLS; c++) {
            // w = log2(mitigation) + log2(compensation); exactly 0 at c==lab
            float w = fmaf(2.0f, fmaxf(y[c] - off, 0.0f), mit[c][lab]);
            y[c] += w;
            mx2 = fmaxf(mx2, y[c]);
        }
        float s2 = 0.0f;
#pragma unroll
        for (int c = 0; c < NCLS; c++) s2 += ex2(y[c] - mx2);
        acc += mx2 + lg2(s2) - yl;                  // nll (base-2 units)
    }

    // block reduction
#pragma unroll
    for (int o = 16; o > 0; o >>= 1) acc += __shfl_xor_sync(0xffffffffu, acc, o);
    if (lane == 0) swarp[warp] = acc;
    __syncthreads();
    if (warp == 0) {
        float v = (lane < MTHR/32) ? swarp[lane] : 0.0f;
#pragma unroll
        for (int o = 4; o > 0; o >>= 1) v += __shfl_xor_sync(0xffffffffu, v, o);
        if (lane == 0) {
            g_pnll[bid] = v;
            __threadfence();
            int old = atomicAdd(&g_done, 1);
            if (old == MBLK - 1) sh_last = 1;
        }
    }
    __syncthreads();

    // last block: final reduce (deterministic order), write out, reset state
    if (sh_last) {
        float v = 0.0f;
#pragma unroll 1
        for (int b = tid; b < MBLK; b += MTHR) v += g_pnll[b];
#pragma unroll
        for (int o = 16; o > 0; o >>= 1) v += __shfl_xor_sync(0xffffffffu, v, o);
        if (lane == 0) swarp[warp] = v;
        __syncthreads();
        if (warp == 0) {
            float t = (lane < MTHR/32) ? swarp[lane] : 0.0f;
#pragma unroll
            for (int o = 4; o > 0; o >>= 1) t += __shfl_xor_sync(0xffffffffu, t, o);
            if (lane == 0)
                out[0] = LN2 * t / (float)(MTOT - g_hist[0]);
        }
        __syncthreads();                // out/g_hist[0] read done before reset
        if (tid < NCLS) g_hist[tid] = 0;
        if (tid == 0)   g_done = 0;
    }
}

extern "C" void kernel_launch(void* const* d_in, const int* in_sizes, int n_in,
                              void* d_out, int out_size) {
    const float* cls  = nullptr;
    const int*   lab  = nullptr;
    const float* cums = nullptr;
    for (int i = 0; i < n_in; i++) {
        if (in_sizes[i] == MTOT * NCLS)  cls  = (const float*)d_in[i];
        else if (in_sizes[i] == MTOT)    lab  = (const int*)d_in[i];
        else if (in_sizes[i] == NCLS)    cums = (const float*)d_in[i];
    }
    if (!cls)  cls  = (const float*)d_in[0];
    if (!lab)  lab  = (const int*)d_in[1];
    if (!cums) cums = (const float*)d_in[2];

    k_hist<<<HBLK, HTHR>>>(lab);
    k_main<<<MBLK, MTHR>>>(cls, lab, cums, (float*)d_out);
    (void)out_size; (void)n_in;
}